// round 11
// baseline (speedup 1.0000x reference)
#include <cuda_runtime.h>
#include <cuda_fp16.h>
#include <cstdint>

#define Bdim 16
#define L 256
#define H 256

typedef unsigned long long ull;

// Scratch (device globals: allocation-free)
__device__ __align__(16) float g_A[Bdim * L * H];      // A[b][q][o] fp32 (= query @ Wq^T)
__device__ __align__(16) ull   g_Cth[Bdim * 64 * 256]; // [b][og][c]: 4 halves = C[c][4og..4og+3] (+bias), fp16

// ---------------- helpers ----------------
__device__ __forceinline__ ull fma2(ull a, ull b, ull c) {
    ull d; asm("fma.rn.f32x2 %0, %1, %2, %3;" : "=l"(d) : "l"(a), "l"(b), "l"(c)); return d;
}
__device__ __forceinline__ ull add2(ull a, ull b) {
    ull d; asm("add.rn.f32x2 %0, %1, %2;" : "=l"(d) : "l"(a), "l"(b)); return d;
}
__device__ __forceinline__ ull pack2(float lo, float hi) {
    ull d; asm("mov.b64 %0, {%1, %2};" : "=l"(d) : "f"(lo), "f"(hi)); return d;
}
__device__ __forceinline__ float2 unpack2(ull a) {
    float2 r; asm("mov.b64 {%0, %1}, %2;" : "=f"(r.x), "=f"(r.y) : "l"(a)); return r;
}
__device__ __forceinline__ float hsum2(ull a) { float2 r = unpack2(a); return r.x + r.y; }

__device__ __forceinline__ __half2 u2h2(unsigned u) { return *reinterpret_cast<__half2*>(&u); }
__device__ __forceinline__ unsigned h2u(__half2 h) { return *reinterpret_cast<unsigned*>(&h); }
__device__ __forceinline__ __half2 h2_lo(ull x) { return u2h2((unsigned)x); }
__device__ __forceinline__ __half2 h2_hi(ull x) { return u2h2((unsigned)(x >> 32)); }
__device__ __forceinline__ ull pack_h4(float f0, float f1, float f2, float f3) {
    __half2 a = __floats2half2_rn(f0, f1);
    __half2 b = __floats2half2_rn(f2, f3);
    return ((ull)h2u(b) << 32) | (ull)h2u(a);
}
// flush helper: add fp16x2 accumulator into fp32x2 accumulator
__device__ __forceinline__ ull flushh(ull f, __half2 h) {
    float2 x = __half22float2(h);
    return add2(f, pack2(x.x, x.y));
}

// ---------------- Projection GEMM (fp16 HFMA2 core, unchanged from R10) ----------------
__global__ __launch_bounds__(256) void proj_kernel(
    const float* __restrict__ query, const float* __restrict__ context,
    const float* __restrict__ W, const float* __restrict__ bias)
{
    __shared__ __align__(16) char smemraw[16896];  // stages (8.7KB) / T (16.5KB) overlay
    __half2 (*As2)[68] = reinterpret_cast<__half2(*)[68]>(smemraw);
    __half2 (*Bs2)[68] = reinterpret_cast<__half2(*)[68]>(smemraw + 4352);
    float* T = reinterpret_cast<float*>(smemraw);

    const int tid = threadIdx.x;
    const int tx = tid & 15;          // n quad
    const int ty = tid >> 4;          // m quad
    const int row0 = blockIdx.x * 64;
    const int n0 = blockIdx.y * 64;
    const int which = blockIdx.z;

    const float* X = which ? context : query;
    const float* Wbase = W + (which ? H : 0);   // row stride 2H

    const __half2 hz = __floats2half2_rn(0.f, 0.f);
    __half2 hacc[4][4];
    ull facc[4][4];
    #pragma unroll
    for (int i = 0; i < 4; i++)
        #pragma unroll
        for (int j = 0; j < 4; j++) { hacc[i][j] = hz; facc[i][j] = 0ULL; }

    for (int kc = 0; kc < H; kc += 32) {   // 16 k-pairs per chunk
        #pragma unroll
        for (int it = 0; it < 4; it++) {
            int i = it * 256 + tid;
            int kp = i & 15, r = i >> 4;   // r 0..63
            float2 xv = *(const float2*)&X[(row0 + r) * H + kc + 2 * kp];
            As2[kp][r] = __floats2half2_rn(xv.x, xv.y);
            float2 wv = *(const float2*)&Wbase[(n0 + r) * (2 * H) + kc + 2 * kp];
            Bs2[kp][r] = __floats2half2_rn(wv.x, wv.y);
        }
        __syncthreads();

        #pragma unroll
        for (int hf = 0; hf < 2; hf++) {
            #pragma unroll
            for (int kk = 0; kk < 8; kk++) {
                const int kp = hf * 8 + kk;
                ulonglong2 av = *(const ulonglong2*)&As2[kp][ty * 4];
                ulonglong2 bv = *(const ulonglong2*)&Bs2[kp][tx * 4];
                __half2 a0 = h2_lo(av.x), a1 = h2_hi(av.x), a2 = h2_lo(av.y), a3 = h2_hi(av.y);
                __half2 b0 = h2_lo(bv.x), b1 = h2_hi(bv.x), b2 = h2_lo(bv.y), b3 = h2_hi(bv.y);
                hacc[0][0] = __hfma2(a0, b0, hacc[0][0]);
                hacc[0][1] = __hfma2(a0, b1, hacc[0][1]);
                hacc[0][2] = __hfma2(a0, b2, hacc[0][2]);
                hacc[0][3] = __hfma2(a0, b3, hacc[0][3]);
                hacc[1][0] = __hfma2(a1, b0, hacc[1][0]);
                hacc[1][1] = __hfma2(a1, b1, hacc[1][1]);
                hacc[1][2] = __hfma2(a1, b2, hacc[1][2]);
                hacc[1][3] = __hfma2(a1, b3, hacc[1][3]);
                hacc[2][0] = __hfma2(a2, b0, hacc[2][0]);
                hacc[2][1] = __hfma2(a2, b1, hacc[2][1]);
                hacc[2][2] = __hfma2(a2, b2, hacc[2][2]);
                hacc[2][3] = __hfma2(a2, b3, hacc[2][3]);
                hacc[3][0] = __hfma2(a3, b0, hacc[3][0]);
                hacc[3][1] = __hfma2(a3, b1, hacc[3][1]);
                hacc[3][2] = __hfma2(a3, b2, hacc[3][2]);
                hacc[3][3] = __hfma2(a3, b3, hacc[3][3]);
            }
            #pragma unroll
            for (int i = 0; i < 4; i++)
                #pragma unroll
                for (int j = 0; j < 4; j++) {
                    facc[i][j] = flushh(facc[i][j], hacc[i][j]);
                    hacc[i][j] = hz;
                }
        }
        __syncthreads();
    }

    if (which == 0) {
        #pragma unroll
        for (int i = 0; i < 4; i++) {
            float4 v = make_float4(hsum2(facc[i][0]), hsum2(facc[i][1]),
                                   hsum2(facc[i][2]), hsum2(facc[i][3]));
            *(float4*)&g_A[(row0 + ty * 4 + i) * H + n0 + tx * 4] = v;
        }
    } else {
        float bv0 = bias[n0 + tx * 4 + 0];
        float bv1 = bias[n0 + tx * 4 + 1];
        float bv2v = bias[n0 + tx * 4 + 2];
        float bv3 = bias[n0 + tx * 4 + 3];
        #pragma unroll
        for (int i = 0; i < 4; i++) {
            int m = ty * 4 + i;
            T[m * 66 + tx * 4 + 0] = hsum2(facc[i][0]) + bv0;
            T[m * 66 + tx * 4 + 1] = hsum2(facc[i][1]) + bv1;
            T[m * 66 + tx * 4 + 2] = hsum2(facc[i][2]) + bv2v;
            T[m * 66 + tx * 4 + 3] = hsum2(facc[i][3]) + bv3;
        }
        __syncthreads();
        const int b = row0 >> 8;
        const int c0 = row0 & 255;
        #pragma unroll
        for (int it = 0; it < 4; it++) {
            int e = it * 256 + tid;
            int m = e & 63;        // c within tile
            int ogl = e >> 6;      // o-group within tile (0..15)
            float f0 = T[m * 66 + 4 * ogl + 0];
            float f1 = T[m * 66 + 4 * ogl + 1];
            float f2 = T[m * 66 + 4 * ogl + 2];
            float f3 = T[m * 66 + 4 * ogl + 3];
            g_Cth[((ull)(b * 64 + (n0 >> 2) + ogl)) * 256 + (c0 + m)] = pack_h4(f0, f1, f2, f3);
        }
    }
}

// ---------------- Fused score + softmax + AV ----------------
// R10 form with the C stream moved to a 4-stage cp.async ring. Each thread
// copies only its own 8B slot -> completion is thread-local after wait_group;
// no barriers in the hot loop.
__global__ __launch_bounds__(256, 4) void score_kernel(
    const float* __restrict__ ctx, const int* __restrict__ mask,
    const float* __restrict__ sw, float* __restrict__ attn_out, float* __restrict__ attn)
{
    __shared__ __align__(16) float Aq[8][256];    // fp32 A (for sq)
    __shared__ __align__(16) float S[8][256];
    __shared__ __align__(16) ull Aqh[8][64];      // fp16 A, 4 o per ull
    __shared__ __align__(16) ull vh2[64];         // fp16 0.495*v, 4 o per ull
    __shared__ __align__(16) ull Cst[4][256];     // cp.async ring (8KB)
    __shared__ float sq_s[8], inv_s[8];

    const int tid = threadIdx.x;
    const int lane = tid & 31;
    const int w = tid >> 5;
    const int b = blockIdx.x >> 5;
    const int q0 = (blockIdx.x & 31) << 3;

    if (tid < 64) {
        float4 s4 = *(const float4*)&sw[4 * tid];
        vh2[tid] = pack_h4(0.495f * s4.x, 0.495f * s4.y, 0.495f * s4.z, 0.495f * s4.w);
    }
    #pragma unroll
    for (int it = 0; it < 2; it++) {
        int fi = it * 256 + tid;
        int q = fi >> 6, o = (fi & 63) << 2;
        float4 v4 = *(const float4*)&g_A[(b * L + q0 + q) * H + o];
        *(float4*)&Aq[q][o] = v4;
        Aqh[q][o >> 2] = pack_h4(v4.x, v4.y, v4.z, v4.w);
    }

    // start the C pipeline before the block barrier (cp.async is independent)
    const ull* CbG = g_Cth + (ull)b * (64 * 256) + tid;
    const uint32_t stb = (uint32_t)__cvta_generic_to_shared(&Cst[0][0]) + (uint32_t)(tid << 3);
    #pragma unroll
    for (int s = 0; s < 3; s++) {
        asm volatile("cp.async.ca.shared.global [%0], [%1], 8;"
                     :: "r"(stb + (uint32_t)(s << 11)), "l"(CbG + s * 256) : "memory");
        asm volatile("cp.async.commit_group;" ::: "memory");
    }
    __syncthreads();

    // sq[q] = sum_o v[o] * A[q][o]   (fp32; warp w handles q = w)
    {
        float s = 0.f;
        #pragma unroll
        for (int j = 0; j < 8; j++) s += sw[lane + 32 * j] * Aq[w][lane + 32 * j];
        #pragma unroll
        for (int off = 16; off; off >>= 1) s += __shfl_xor_sync(0xffffffffu, s, off);
        if (lane == 0) sq_s[w] = s;
    }

    // ---- fp16 main score loop ----
    const __half2 hz = __floats2half2_rn(0.f, 0.f);
    __half2 hq01[8], hq23[8];
    ull facc[8];
    #pragma unroll
    for (int q = 0; q < 8; q++) { hq01[q] = hz; hq23[q] = hz; facc[q] = 0ULL; }
    __half2 hl01 = hz, hl23 = hz;
    ull flin = 0ULL;

    for (int blk = 0; blk < 8; blk++) {
        #pragma unroll
        for (int j = 0; j < 8; j++) {
            const int og = blk * 8 + j;
            if (og < 61) {
                asm volatile("cp.async.ca.shared.global [%0], [%1], 8;"
                             :: "r"(stb + (uint32_t)(((og + 3) & 3) << 11)), "l"(CbG + (og + 3) * 256) : "memory");
            }
            asm volatile("cp.async.commit_group;" ::: "memory");
            asm volatile("cp.async.wait_group 3;" ::: "memory");

            ull c4 = Cst[og & 3][tid];
            __half2 c01 = h2_lo(c4), c23 = h2_hi(c4);
            ull v4 = vh2[og];
            __half2 v01 = h2_lo(v4), v23 = h2_hi(v4);
            hl01 = __hfma2(c01, v01, hl01);
            hl23 = __hfma2(c23, v23, hl23);
            #pragma unroll
            for (int q = 0; q < 8; q++) {
                ull a4 = Aqh[q][og];
                __half2 t01 = __hadd2(h2_lo(a4), c01);
                __half2 t23 = __hadd2(h2_hi(a4), c23);
                hq01[q] = __hfma2(__habs2(t01), v01, hq01[q]);
                hq23[q] = __hfma2(__habs2(t23), v23, hq23[q]);
            }
        }
        // fp32 flush (limits fp16 accumulation error)
        #pragma unroll
        for (int q = 0; q < 8; q++) {
            facc[q] = flushh(facc[q], __hadd2(hq01[q], hq23[q]));
            hq01[q] = hz; hq23[q] = hz;
        }
        flin = flushh(flin, __hadd2(hl01, hl23));
        hl01 = hz; hl23 = hz;
    }
    __syncthreads();   // sq_s ready

    const int mk = mask[b * L + tid];
    const float sc_scaled = hsum2(flin);            // = 0.495 * sum_o C*v
    const float NEG_INF = __int_as_float(0xff800000u);
    #pragma unroll
    for (int q = 0; q < 8; q++) {
        float s = 0.505f * sq_s[q] + 1.02020202f * sc_scaled + hsum2(facc[q]);
        if (mk == 0) s = NEG_INF;
        S[q][tid] = s;
    }
    __syncthreads();

    // softmax: warp w reduces row q = w (fp32)
    {
        float m = NEG_INF;
        #pragma unroll
        for (int j = 0; j < 8; j++) m = fmaxf(m, S[w][lane + 32 * j]);
        #pragma unroll
        for (int off = 16; off; off >>= 1) m = fmaxf(m, __shfl_xor_sync(0xffffffffu, m, off));
        float ssum = 0.f;
        #pragma unroll
        for (int j = 0; j < 8; j++) {
            float e = __expf(S[w][lane + 32 * j] - m);
            S[w][lane + 32 * j] = e;
            ssum += e;
        }
        #pragma unroll
        for (int off = 16; off; off >>= 1) ssum += __shfl_xor_sync(0xffffffffu, ssum, off);
        if (lane == 0) inv_s[w] = 1.f / ssum;
    }
    __syncthreads();

    // scale + write attn (coalesced STG.32 per q-row)
    #pragma unroll
    for (int q = 0; q < 8; q++) {
        float a = S[q][tid] * inv_s[q];
        S[q][tid] = a;
        attn[(b * L + q0 + q) * L + tid] = a;
    }
    __syncthreads();

    // AV: out[q][h=tid] = sum_c attn[q][c] * ctx[b][c][h] (fp32, reg prefetch)
    ull av[8];
    #pragma unroll
    for (int q = 0; q < 8; q++) av[q] = 0ULL;
    const float* cb = ctx + b * (L * H) + tid;
    float n0v = cb[0], n1v = cb[H], n2v = cb[2 * H], n3v = cb[3 * H];
    #pragma unroll 2
    for (int cg = 0; cg < 64; cg++) {
        float x0 = n0v, x1 = n1v, x2 = n2v, x3 = n3v;
        int nc = ((cg + 1) & 63) * 4;
        n0v = cb[nc * H]; n1v = cb[(nc + 1) * H];
        n2v = cb[(nc + 2) * H]; n3v = cb[(nc + 3) * H];
        ull cc01 = pack2(x0, x1);
        ull cc23 = pack2(x2, x3);
        #pragma unroll
        for (int q = 0; q < 8; q++) {
            ulonglong2 a = *(const ulonglong2*)&S[q][cg << 2];
            av[q] = fma2(a.x, cc01, av[q]);
            av[q] = fma2(a.y, cc23, av[q]);
        }
    }
    #pragma unroll
    for (int q = 0; q < 8; q++) {
        attn_out[(b * L + q0 + q) * H + tid] = hsum2(av[q]);
    }
}

extern "C" void kernel_launch(void* const* d_in, const int* in_sizes, int n_in,
                              void* d_out, int out_size)
{
    const float* query   = (const float*)d_in[0];
    const float* context = (const float*)d_in[1];
    const int*   mask    = (const int*)d_in[2];
    const float* w       = (const float*)d_in[3];
    const float* bias    = (const float*)d_in[4];
    const float* sw      = (const float*)d_in[5];

    float* out = (float*)d_out;
    float* attn_out = out;                      // (B, Lq, H)
    float* attn     = out + Bdim * L * H;       // (B, Lq, Lc)

    dim3 pgrid(64, 4, 2);
    proj_kernel<<<pgrid, 256>>>(query, context, w, bias);
    score_kernel<<<512, 256>>>(context, mask, sw, attn_out, attn);
}

// round 12
// speedup vs baseline: 1.2727x; 1.2727x over previous
#include <cuda_runtime.h>
#include <cuda_fp16.h>
#include <cstdint>

#define Bdim 16
#define L 256
#define H 256

typedef unsigned long long ull;

// Scratch (device globals: allocation-free)
__device__ __align__(16) float g_A[Bdim * L * H];      // A[b][q][o] fp32 (= query @ Wq^T)
__device__ __align__(16) ull   g_Cth[Bdim * 64 * 256]; // [b][og][c]: 4 halves = C[c][4og..4og+3] (+bias), fp16

// ---------------- helpers ----------------
__device__ __forceinline__ ull fma2(ull a, ull b, ull c) {
    ull d; asm("fma.rn.f32x2 %0, %1, %2, %3;" : "=l"(d) : "l"(a), "l"(b), "l"(c)); return d;
}
__device__ __forceinline__ ull add2(ull a, ull b) {
    ull d; asm("add.rn.f32x2 %0, %1, %2;" : "=l"(d) : "l"(a), "l"(b)); return d;
}
__device__ __forceinline__ ull pack2(float lo, float hi) {
    ull d; asm("mov.b64 %0, {%1, %2};" : "=l"(d) : "f"(lo), "f"(hi)); return d;
}
__device__ __forceinline__ float2 unpack2(ull a) {
    float2 r; asm("mov.b64 {%0, %1}, %2;" : "=f"(r.x), "=f"(r.y) : "l"(a)); return r;
}
__device__ __forceinline__ float hsum2(ull a) { float2 r = unpack2(a); return r.x + r.y; }

__device__ __forceinline__ __half2 u2h2(unsigned u) { return *reinterpret_cast<__half2*>(&u); }
__device__ __forceinline__ unsigned h2u(__half2 h) { return *reinterpret_cast<unsigned*>(&h); }
__device__ __forceinline__ __half2 h2_lo(ull x) { return u2h2((unsigned)x); }
__device__ __forceinline__ __half2 h2_hi(ull x) { return u2h2((unsigned)(x >> 32)); }
__device__ __forceinline__ __half2 habs_lop(__half2 x) { return u2h2(h2u(x) & 0x7FFF7FFFu); }
__device__ __forceinline__ ull pack_h4(float f0, float f1, float f2, float f3) {
    __half2 a = __floats2half2_rn(f0, f1);
    __half2 b = __floats2half2_rn(f2, f3);
    return ((ull)h2u(b) << 32) | (ull)h2u(a);
}
__device__ __forceinline__ ull flushh(ull f, __half2 h) {
    float2 x = __half22float2(h);
    return add2(f, pack2(x.x, x.y));
}

// m16n8k16 fp16 MMA, fp32 accumulate in-place
__device__ __forceinline__ void mma16816(float* d, unsigned a0, unsigned a1,
                                         unsigned a2, unsigned a3,
                                         unsigned b0, unsigned b1) {
    asm volatile(
        "mma.sync.aligned.m16n8k16.row.col.f32.f16.f16.f32 "
        "{%0,%1,%2,%3}, {%4,%5,%6,%7}, {%8,%9}, {%0,%1,%2,%3};"
        : "+f"(d[0]), "+f"(d[1]), "+f"(d[2]), "+f"(d[3])
        : "r"(a0), "r"(a1), "r"(a2), "r"(a3), "r"(b0), "r"(b1));
}

// ---------------- Projection GEMM (HMMA tensor cores) ----------------
// D = X @ W^T. 64x64 tile per block, 8 warps = 4 m16 x 2 n32.
// smem: X/W tiles as fp16, row-major [64][64] halves, row stride 72.
#define XS_STRIDE 72

__global__ __launch_bounds__(256) void proj_kernel(
    const float* __restrict__ query, const float* __restrict__ context,
    const float* __restrict__ W, const float* __restrict__ bias)
{
    __shared__ __align__(16) char smemraw[18688];  // Xs(9216)+Ws(9216) / T(16896) overlay
    __half* Xs = reinterpret_cast<__half*>(smemraw);
    __half* Ws = reinterpret_cast<__half*>(smemraw + 9216);
    float* T = reinterpret_cast<float*>(smemraw);

    const int tid = threadIdx.x;
    const int lane = tid & 31;
    const int w = tid >> 5;
    const int gid = lane >> 2;        // 0..7
    const int tig = lane & 3;         // 0..3
    const int wm = w & 3;             // m16 tile index
    const int wn = w >> 2;            // n32 tile index
    const int row0 = blockIdx.x * 64;
    const int n0 = blockIdx.y * 64;
    const int which = blockIdx.z;

    const float* X = which ? context : query;
    const float* Wbase = W + (which ? H : 0);   // row stride 2H

    float acc[4][4];                  // [jn][reg]
    #pragma unroll
    for (int j = 0; j < 4; j++)
        #pragma unroll
        for (int r = 0; r < 4; r++) acc[j][r] = 0.f;

    for (int kc = 0; kc < H; kc += 64) {   // 64-k chunks, 4 k16 steps each
        // stage X and W tiles as fp16 (coalesced float2 reads)
        #pragma unroll
        for (int it = 0; it < 8; it++) {
            int i = it * 256 + tid;
            int kp = i & 31, r = i >> 5;   // r 0..63, kp half2-col 0..31
            float2 xv = *(const float2*)&X[(row0 + r) * H + kc + 2 * kp];
            *reinterpret_cast<__half2*>(&Xs[r * XS_STRIDE + 2 * kp]) = __floats2half2_rn(xv.x, xv.y);
            float2 wv = *(const float2*)&Wbase[(n0 + r) * (2 * H) + kc + 2 * kp];
            *reinterpret_cast<__half2*>(&Ws[r * XS_STRIDE + 2 * kp]) = __floats2half2_rn(wv.x, wv.y);
        }
        __syncthreads();

        #pragma unroll
        for (int ks = 0; ks < 4; ks++) {
            const int k0 = ks * 16;
            const int ra = wm * 16 + gid;
            unsigned a0 = *(const unsigned*)&Xs[ra * XS_STRIDE + k0 + 2 * tig];
            unsigned a1 = *(const unsigned*)&Xs[(ra + 8) * XS_STRIDE + k0 + 2 * tig];
            unsigned a2 = *(const unsigned*)&Xs[ra * XS_STRIDE + k0 + 2 * tig + 8];
            unsigned a3 = *(const unsigned*)&Xs[(ra + 8) * XS_STRIDE + k0 + 2 * tig + 8];
            #pragma unroll
            for (int jn = 0; jn < 4; jn++) {
                const int rb = wn * 32 + jn * 8 + gid;
                unsigned b0 = *(const unsigned*)&Ws[rb * XS_STRIDE + k0 + 2 * tig];
                unsigned b1 = *(const unsigned*)&Ws[rb * XS_STRIDE + k0 + 2 * tig + 8];
                mma16816(acc[jn], a0, a1, a2, a3, b0, b1);
            }
        }
        __syncthreads();
    }

    const int mrow = wm * 16 + gid;       // local m row (and +8)
    if (which == 0) {
        #pragma unroll
        for (int jn = 0; jn < 4; jn++) {
            const int ncol = n0 + wn * 32 + jn * 8 + tig * 2;
            *(float2*)&g_A[(row0 + mrow) * H + ncol] = make_float2(acc[jn][0], acc[jn][1]);
            *(float2*)&g_A[(row0 + mrow + 8) * H + ncol] = make_float2(acc[jn][2], acc[jn][3]);
        }
    } else {
        #pragma unroll
        for (int jn = 0; jn < 4; jn++) {
            const int ncl = wn * 32 + jn * 8 + tig * 2;
            float2 bv = *(const float2*)&bias[n0 + ncl];
            T[mrow * 66 + ncl] = acc[jn][0] + bv.x;
            T[mrow * 66 + ncl + 1] = acc[jn][1] + bv.y;
            T[(mrow + 8) * 66 + ncl] = acc[jn][2] + bv.x;
            T[(mrow + 8) * 66 + ncl + 1] = acc[jn][3] + bv.y;
        }
        __syncthreads();
        const int b = row0 >> 8;
        const int c0 = row0 & 255;
        #pragma unroll
        for (int it = 0; it < 4; it++) {
            int e = it * 256 + tid;
            int m = e & 63;        // c within tile
            int ogl = e >> 6;      // o-group within tile (0..15)
            float f0 = T[m * 66 + 4 * ogl + 0];
            float f1 = T[m * 66 + 4 * ogl + 1];
            float f2 = T[m * 66 + 4 * ogl + 2];
            float f3 = T[m * 66 + 4 * ogl + 3];
            g_Cth[((ull)(b * 64 + (n0 >> 2) + ogl)) * 256 + (c0 + m)] = pack_h4(f0, f1, f2, f3);
        }
    }
}

// ---------------- Fused score + softmax + AV (R8 loop, abs on ALU pipe) ----------------
__global__ __launch_bounds__(256, 4) void score_kernel(
    const float* __restrict__ ctx, const int* __restrict__ mask,
    const float* __restrict__ sw, float* __restrict__ attn_out, float* __restrict__ attn)
{
    __shared__ __align__(16) float Aq[8][256];    // fp32 A (for sq)
    __shared__ __align__(16) float S[8][256];
    __shared__ __align__(16) ull Aqh[8][64];      // fp16 A, 4 o per ull
    __shared__ __align__(16) ull vh2[64];         // fp16 0.495*v, 4 o per ull
    __shared__ float sq_s[8], inv_s[8];

    const int tid = threadIdx.x;
    const int lane = tid & 31;
    const int w = tid >> 5;
    const int b = blockIdx.x >> 5;
    const int q0 = (blockIdx.x & 31) << 3;

    if (tid < 64) {
        float4 s4 = *(const float4*)&sw[4 * tid];
        vh2[tid] = pack_h4(0.495f * s4.x, 0.495f * s4.y, 0.495f * s4.z, 0.495f * s4.w);
    }
    #pragma unroll
    for (int it = 0; it < 2; it++) {
        int fi = it * 256 + tid;
        int q = fi >> 6, o = (fi & 63) << 2;
        float4 v4 = *(const float4*)&g_A[(b * L + q0 + q) * H + o];
        *(float4*)&Aq[q][o] = v4;
        Aqh[q][o >> 2] = pack_h4(v4.x, v4.y, v4.z, v4.w);
    }
    __syncthreads();

    // sq[q] = sum_o v[o] * A[q][o]   (fp32; warp w handles q = w)
    {
        float s = 0.f;
        #pragma unroll
        for (int j = 0; j < 8; j++) s += sw[lane + 32 * j] * Aq[w][lane + 32 * j];
        #pragma unroll
        for (int off = 16; off; off >>= 1) s += __shfl_xor_sync(0xffffffffu, s, off);
        if (lane == 0) sq_s[w] = s;
    }

    // ---- fp16 main score loop ----
    const __half2 hz = __floats2half2_rn(0.f, 0.f);
    __half2 hq01[8], hq23[8];
    ull facc[8];
    #pragma unroll
    for (int q = 0; q < 8; q++) { hq01[q] = hz; hq23[q] = hz; facc[q] = 0ULL; }
    __half2 hl01 = hz, hl23 = hz;
    ull flin = 0ULL;

    const ull* Cb = g_Cth + (ull)b * (64 * 256) + tid;
    ull p0 = Cb[0];
    ull p1 = Cb[256];

    for (int blk = 0; blk < 8; blk++) {
        #pragma unroll
        for (int j = 0; j < 8; j++) {
            const int og = blk * 8 + j;
            ull c4 = p0;
            p0 = p1;
            p1 = Cb[((og + 2) & 63) * 256];
            __half2 c01 = h2_lo(c4), c23 = h2_hi(c4);
            ull v4 = vh2[og];
            __half2 v01 = h2_lo(v4), v23 = h2_hi(v4);
            hl01 = __hfma2(c01, v01, hl01);
            hl23 = __hfma2(c23, v23, hl23);
            #pragma unroll
            for (int q = 0; q < 8; q++) {
                ull a4 = Aqh[q][og];
                __half2 t01 = habs_lop(__hadd2(h2_lo(a4), c01));
                __half2 t23 = habs_lop(__hadd2(h2_hi(a4), c23));
                hq01[q] = __hfma2(t01, v01, hq01[q]);
                hq23[q] = __hfma2(t23, v23, hq23[q]);
            }
        }
        // fp32 flush (limits fp16 accumulation error)
        #pragma unroll
        for (int q = 0; q < 8; q++) {
            facc[q] = flushh(facc[q], __hadd2(hq01[q], hq23[q]));
            hq01[q] = hz; hq23[q] = hz;
        }
        flin = flushh(flin, __hadd2(hl01, hl23));
        hl01 = hz; hl23 = hz;
    }
    __syncthreads();   // sq_s ready

    const int mk = mask[b * L + tid];
    const float sc_scaled = hsum2(flin);            // = 0.495 * sum_o C*v
    const float NEG_INF = __int_as_float(0xff800000u);
    #pragma unroll
    for (int q = 0; q < 8; q++) {
        float s = 0.505f * sq_s[q] + 1.02020202f * sc_scaled + hsum2(facc[q]);
        if (mk == 0) s = NEG_INF;
        S[q][tid] = s;
    }
    __syncthreads();

    // softmax: warp w reduces row q = w (fp32)
    {
        float m = NEG_INF;
        #pragma unroll
        for (int j = 0; j < 8; j++) m = fmaxf(m, S[w][lane + 32 * j]);
        #pragma unroll
        for (int off = 16; off; off >>= 1) m = fmaxf(m, __shfl_xor_sync(0xffffffffu, m, off));
        float ssum = 0.f;
        #pragma unroll
        for (int j = 0; j < 8; j++) {
            float e = __expf(S[w][lane + 32 * j] - m);
            S[w][lane + 32 * j] = e;
            ssum += e;
        }
        #pragma unroll
        for (int off = 16; off; off >>= 1) ssum += __shfl_xor_sync(0xffffffffu, ssum, off);
        if (lane == 0) inv_s[w] = 1.f / ssum;
    }
    __syncthreads();

    // scale + write attn (coalesced STG.32 per q-row)
    #pragma unroll
    for (int q = 0; q < 8; q++) {
        float a = S[q][tid] * inv_s[q];
        S[q][tid] = a;
        attn[(b * L + q0 + q) * L + tid] = a;
    }
    __syncthreads();

    // AV: out[q][h=tid] = sum_c attn[q][c] * ctx[b][c][h] (fp32, reg prefetch)
    ull av[8];
    #pragma unroll
    for (int q = 0; q < 8; q++) av[q] = 0ULL;
    const float* cb = ctx + b * (L * H) + tid;
    float n0v = cb[0], n1v = cb[H], n2v = cb[2 * H], n3v = cb[3 * H];
    #pragma unroll 2
    for (int cg = 0; cg < 64; cg++) {
        float x0 = n0v, x1 = n1v, x2 = n2v, x3 = n3v;
        int nc = ((cg + 1) & 63) * 4;
        n0v = cb[nc * H]; n1v = cb[(nc + 1) * H];
        n2v = cb[(nc + 2) * H]; n3v = cb[(nc + 3) * H];
        ull cc01 = pack2(x0, x1);
        ull cc23 = pack2(x2, x3);
        #pragma unroll
        for (int q = 0; q < 8; q++) {
            ulonglong2 a = *(const ulonglong2*)&S[q][cg << 2];
            av[q] = fma2(a.x, cc01, av[q]);
            av[q] = fma2(a.y, cc23, av[q]);
        }
    }
    #pragma unroll
    for (int q = 0; q < 8; q++) {
        attn_out[(b * L + q0 + q) * H + tid] = hsum2(av[q]);
    }
}

extern "C" void kernel_launch(void* const* d_in, const int* in_sizes, int n_in,
                              void* d_out, int out_size)
{
    const float* query   = (const float*)d_in[0];
    const float* context = (const float*)d_in[1];
    const int*   mask    = (const int*)d_in[2];
    const float* w       = (const float*)d_in[3];
    const float* bias    = (const float*)d_in[4];
    const float* sw      = (const float*)d_in[5];

    float* out = (float*)d_out;
    float* attn_out = out;                      // (B, Lq, H)
    float* attn     = out + Bdim * L * H;       // (B, Lq, Lc)

    dim3 pgrid(64, 4, 2);
    proj_kernel<<<pgrid, 256>>>(query, context, w, bias);
    score_kernel<<<512, 256>>>(context, mask, sw, attn_out, attn);
}